// round 6
// baseline (speedup 1.0000x reference)
#include <cuda_runtime.h>
#include <cuda_bf16.h>

// ---------------- problem constants ----------------
#define NN 100000
#define NE 1600000
#define DD 128

// ---------------- device scratch (static globals; no allocation allowed) ----
__device__ int   g_deg[NN];
__device__ int   g_incl[NN];
__device__ int   g_rowptr[NN + 1];
__device__ int   g_fill[NN];
__device__ int   g_bsum[128];
__device__ int   g_boff[128];
__device__ int   g_csr[NE];
__device__ float g_invdeg[NN];
__device__ float g_hn[(size_t)NN * DD];   // neighbor aggregate (reused both layers)
__device__ float g_h1[(size_t)NN * DD];   // layer-0 output (post LN+ReLU)

// packed f32x2 FMA: d = a*b + d on both 32-bit halves (Blackwell FFMA2)
#define FFMA2(d, a, b) \
    asm volatile("fma.rn.f32x2 %0, %1, %2, %0;" : "+l"(d) : "l"(a), "l"(b))

// ---------------- CSR build ----------------
__global__ void k_init(const int* __restrict__ indeg, int N) {
    int i = blockIdx.x * blockDim.x + threadIdx.x;
    if (i < N) {
        g_deg[i] = 0;
        int d = indeg[i];
        if (d < 1) d = 1;
        g_invdeg[i] = 1.0f / (float)d;
    }
}

__global__ void k_count(const int* __restrict__ edst, int E) {
    int e = blockIdx.x * blockDim.x + threadIdx.x;
    if (e < E) atomicAdd(&g_deg[edst[e]], 1);
}

__global__ void k_scan1(int N) {
    __shared__ int s[1024];
    int t = threadIdx.x;
    int i = blockIdx.x * 1024 + t;
    int v = (i < N) ? g_deg[i] : 0;
    s[t] = v;
    __syncthreads();
    #pragma unroll
    for (int off = 1; off < 1024; off <<= 1) {
        int x = (t >= off) ? s[t - off] : 0;
        __syncthreads();
        s[t] += x;
        __syncthreads();
    }
    if (i < N) g_incl[i] = s[t];
    if (t == 1023) g_bsum[blockIdx.x] = s[1023];
}

__global__ void k_scan2(int nb) {
    __shared__ int s[128];
    int t = threadIdx.x;
    int v = (t < nb) ? g_bsum[t] : 0;
    s[t] = v;
    __syncthreads();
    #pragma unroll
    for (int off = 1; off < 128; off <<= 1) {
        int x = (t >= off) ? s[t - off] : 0;
        __syncthreads();
        s[t] += x;
        __syncthreads();
    }
    g_boff[t] = s[t] - v;  // exclusive
}

__global__ void k_scan3(int N) {
    int i = blockIdx.x * blockDim.x + threadIdx.x;
    if (i < N) {
        int b = i >> 10;
        int d = g_deg[i];
        int excl = g_incl[i] - d + g_boff[b];
        g_rowptr[i] = excl;
        g_fill[i]   = excl;
        if (i == N - 1) g_rowptr[N] = excl + d;
    }
}

__global__ void k_fill(const int* __restrict__ esrc, const int* __restrict__ edst, int E) {
    int e = blockIdx.x * blockDim.x + threadIdx.x;
    if (e < E) {
        int d = edst[e];
        int pos = atomicAdd(&g_fill[d], 1);
        g_csr[pos] = esrc[e];
    }
}

// ---------------- neighbor mean aggregation: warp per node ----------------
__global__ void k_agg(const float* __restrict__ h, float* __restrict__ outn, int N) {
    int w = (blockIdx.x * blockDim.x + threadIdx.x) >> 5;
    int lane = threadIdx.x & 31;
    if (w >= N) return;
    int s0 = g_rowptr[w];
    int s1 = g_rowptr[w + 1];
    float4 acc = make_float4(0.f, 0.f, 0.f, 0.f);
    for (int base = s0; base < s1; base += 32) {
        int n = s1 - base;
        if (n > 32) n = 32;
        int sid = (base + lane < s1) ? g_csr[base + lane] : 0;
        #pragma unroll 4
        for (int j = 0; j < n; ++j) {
            int s = __shfl_sync(0xffffffffu, sid, j);
            float4 v = __ldg((const float4*)(h + (size_t)s * DD) + lane);
            acc.x += v.x; acc.y += v.y; acc.z += v.z; acc.w += v.w;
        }
    }
    float iv = g_invdeg[w];
    float4 r = make_float4(acc.x * iv, acc.y * iv, acc.z * iv, acc.w * iv);
    *((float4*)(outn + (size_t)w * DD) + lane) = r;
}

// ---------------- fused dual-GEMM (+bias, optional LN+ReLU) ----------------
// out[r,:] = X[r,:]@Wx + Y[r,:]@Wy + bias ; optional row LayerNorm + ReLU.
// CTA: 256 thr (16x16), tile 128 rows x 128 cols, thread 8x8, f32x2 FMAs.
// Two phases: phase0 = (X,Wx) k=0..127, phase1 = (Y,Wy) k=0..127, acc carried.
__global__ __launch_bounds__(256, 2)
void k_gemm(const float* __restrict__ X, const float* __restrict__ Y,
            const float* __restrict__ Wx, const float* __restrict__ Wy,
            const float* __restrict__ bias,
            const float* __restrict__ lng, const float* __restrict__ lnb,
            float* __restrict__ out, int M, int do_ln) {
    extern __shared__ float sm[];
    float* Bs = sm;              // [128][128] floats = 16384
    float* As = sm + 16384;      // 2 buffers x [16][256] (duplicated pairs) = 8192

    const int t  = threadIdx.x;
    const int tx = t & 15;       // col group
    const int ty = t >> 4;       // row group
    const int m0 = blockIdx.x * 128;

    unsigned long long acc[8][4];
    #pragma unroll
    for (int i = 0; i < 8; ++i)
        #pragma unroll
        for (int j = 0; j < 4; ++j) acc[i][j] = 0ull;

    float4 pA[2];

    for (int p = 0; p < 2; ++p) {
        const float* Ap = p ? Y : X;
        const float* Wp = p ? Wy : Wx;
        __syncthreads();  // prior phase finished reading Bs/As
        // stage W (128x128) into Bs
        {
            const float4* w4 = (const float4*)Wp;
            float4* b4 = (float4*)Bs;
            #pragma unroll
            for (int i = 0; i < 16; ++i) b4[t + i * 256] = w4[t + i * 256];
        }
        // prefetch chunk 0 of A
        {
            #pragma unroll
            for (int it = 0; it < 2; ++it) {
                int idx = t + it * 256;
                int r = idx >> 2, q = idx & 3;
                int rg = m0 + r;
                pA[it] = (rg < M) ? *(const float4*)(Ap + (size_t)rg * DD + q * 4)
                                  : make_float4(0.f, 0.f, 0.f, 0.f);
            }
        }
        // store chunk 0 (duplicated) into buffer 0
        {
            float2* a2 = (float2*)As;  // buffer 0
            #pragma unroll
            for (int it = 0; it < 2; ++it) {
                int idx = t + it * 256;
                int r = idx >> 2, q = idx & 3;
                float2* b = a2 + (q * 4) * 128 + r;
                b[0]   = make_float2(pA[it].x, pA[it].x);
                b[128] = make_float2(pA[it].y, pA[it].y);
                b[256] = make_float2(pA[it].z, pA[it].z);
                b[384] = make_float2(pA[it].w, pA[it].w);
            }
        }
        __syncthreads();

        for (int kc = 0; kc < 8; ++kc) {
            int buf = kc & 1;
            if (kc < 7) {
                int koff = (kc + 1) * 16;
                #pragma unroll
                for (int it = 0; it < 2; ++it) {
                    int idx = t + it * 256;
                    int r = idx >> 2, q = idx & 3;
                    int rg = m0 + r;
                    pA[it] = (rg < M) ? *(const float4*)(Ap + (size_t)rg * DD + koff + q * 4)
                                      : make_float4(0.f, 0.f, 0.f, 0.f);
                }
            }
            // compute 16 k-steps from buffer `buf`
            {
                const ulonglong2* Bs2 = (const ulonglong2*)Bs;
                const ulonglong2* As2 = (const ulonglong2*)(As + buf * 4096);
                #pragma unroll
                for (int kk = 0; kk < 16; ++kk) {
                    int kb = kc * 16 + kk;
                    ulonglong2 b0 = Bs2[kb * 32 + tx * 2];
                    ulonglong2 b1 = Bs2[kb * 32 + tx * 2 + 1];
                    ulonglong2 a0 = As2[kk * 64 + ty * 4 + 0];
                    ulonglong2 a1 = As2[kk * 64 + ty * 4 + 1];
                    ulonglong2 a2 = As2[kk * 64 + ty * 4 + 2];
                    ulonglong2 a3 = As2[kk * 64 + ty * 4 + 3];
                    unsigned long long aa[8] = {a0.x, a0.y, a1.x, a1.y,
                                                a2.x, a2.y, a3.x, a3.y};
                    unsigned long long bb[4] = {b0.x, b0.y, b1.x, b1.y};
                    #pragma unroll
                    for (int i = 0; i < 8; ++i)
                        #pragma unroll
                        for (int j = 0; j < 4; ++j) FFMA2(acc[i][j], aa[i], bb[j]);
                }
            }
            if (kc < 7) {
                float2* a2 = (float2*)(As + (buf ^ 1) * 4096);
                #pragma unroll
                for (int it = 0; it < 2; ++it) {
                    int idx = t + it * 256;
                    int r = idx >> 2, q = idx & 3;
                    float2* b = a2 + (q * 4) * 128 + r;
                    b[0]   = make_float2(pA[it].x, pA[it].x);
                    b[128] = make_float2(pA[it].y, pA[it].y);
                    b[256] = make_float2(pA[it].z, pA[it].z);
                    b[384] = make_float2(pA[it].w, pA[it].w);
                }
                __syncthreads();
            }
        }
    }

    // ---------------- epilogue ----------------
    float bias8[8], g8[8], lb8[8];
    {
        float4 b0 = __ldg((const float4*)(bias + tx * 8));
        float4 b1 = __ldg((const float4*)(bias + tx * 8) + 1);
        bias8[0] = b0.x; bias8[1] = b0.y; bias8[2] = b0.z; bias8[3] = b0.w;
        bias8[4] = b1.x; bias8[5] = b1.y; bias8[6] = b1.z; bias8[7] = b1.w;
    }
    if (do_ln) {
        float4 gv0 = __ldg((const float4*)(lng + tx * 8));
        float4 gv1 = __ldg((const float4*)(lng + tx * 8) + 1);
        float4 bv0 = __ldg((const float4*)(lnb + tx * 8));
        float4 bv1 = __ldg((const float4*)(lnb + tx * 8) + 1);
        g8[0] = gv0.x; g8[1] = gv0.y; g8[2] = gv0.z; g8[3] = gv0.w;
        g8[4] = gv1.x; g8[5] = gv1.y; g8[6] = gv1.z; g8[7] = gv1.w;
        lb8[0] = bv0.x; lb8[1] = bv0.y; lb8[2] = bv0.z; lb8[3] = bv0.w;
        lb8[4] = bv1.x; lb8[5] = bv1.y; lb8[6] = bv1.z; lb8[7] = bv1.w;
    }

    #pragma unroll
    for (int i = 0; i < 8; ++i) {
        float c[8];
        #pragma unroll
        for (int j = 0; j < 4; ++j) {
            c[2 * j]     = __int_as_float((unsigned)(acc[i][j] & 0xffffffffull)) + bias8[2 * j];
            c[2 * j + 1] = __int_as_float((unsigned)(acc[i][j] >> 32))           + bias8[2 * j + 1];
        }
        if (do_ln) {
            float s = 0.f, s2 = 0.f;
            #pragma unroll
            for (int j = 0; j < 8; ++j) { s += c[j]; s2 += c[j] * c[j]; }
            // reduce across the 16 lanes (tx) sharing this row
            #pragma unroll
            for (int d = 1; d < 16; d <<= 1) {
                s  += __shfl_xor_sync(0xffffffffu, s, d);
                s2 += __shfl_xor_sync(0xffffffffu, s2, d);
            }
            float mu  = s * (1.0f / 128.0f);
            float var = s2 * (1.0f / 128.0f) - mu * mu;
            float rs  = rsqrtf(var + 1e-5f);
            #pragma unroll
            for (int j = 0; j < 8; ++j) {
                float v = (c[j] - mu) * rs * g8[j] + lb8[j];
                c[j] = fmaxf(v, 0.f);
            }
        }
        int rg = m0 + ty * 8 + i;
        if (rg < M) {
            float4 o0 = make_float4(c[0], c[1], c[2], c[3]);
            float4 o1 = make_float4(c[4], c[5], c[6], c[7]);
            float* dst = out + (size_t)rg * DD + tx * 8;
            *(float4*)dst = o0;
            *(float4*)(dst + 4) = o1;
        }
    }
}

// ---------------- launch ----------------
extern "C" void kernel_launch(void* const* d_in, const int* in_sizes, int n_in,
                              void* d_out, int out_size) {
    const float* feat = (const float*)d_in[0];
    const float* Ws0  = (const float*)d_in[1];
    const float* Wn0  = (const float*)d_in[2];
    const float* b0   = (const float*)d_in[3];
    const float* Ws1  = (const float*)d_in[4];
    const float* Wn1  = (const float*)d_in[5];
    const float* b1   = (const float*)d_in[6];
    const float* lng  = (const float*)d_in[7];
    const float* lnb  = (const float*)d_in[8];
    const int* esrc   = (const int*)d_in[9];
    const int* edst   = (const int*)d_in[10];
    const int* indeg  = (const int*)d_in[11];
    float* out = (float*)d_out;

    const int N = in_sizes[11];
    const int E = in_sizes[9];
    const int NB = (N + 1023) / 1024;

    const int smem_gemm = (16384 + 8192) * 4;  // 96 KB
    cudaFuncSetAttribute(k_gemm, cudaFuncAttributeMaxDynamicSharedMemorySize, smem_gemm);

    float* hn = nullptr; float* h1 = nullptr;
    cudaGetSymbolAddress((void**)&hn, g_hn);
    cudaGetSymbolAddress((void**)&h1, g_h1);

    // CSR build
    k_init <<<(N + 255) / 256, 256>>>(indeg, N);
    k_count<<<(E + 255) / 256, 256>>>(edst, E);
    k_scan1<<<NB, 1024>>>(N);
    k_scan2<<<1, 128>>>(NB);
    k_scan3<<<(N + 255) / 256, 256>>>(N);
    k_fill <<<(E + 255) / 256, 256>>>(esrc, edst, E);

    const int gemm_grid = (N + 127) / 128;

    // layer 0: aggregate feat -> hn ; h1 = relu(LN(feat@Ws0 + hn@Wn0 + b0))
    k_agg<<<(N + 7) / 8, 256>>>(feat, hn, N);
    k_gemm<<<gemm_grid, 256, smem_gemm>>>(feat, hn, Ws0, Wn0, b0, lng, lnb, h1, N, 1);

    // layer 1: aggregate h1 -> hn ; out = h1@Ws1 + hn@Wn1 + b1
    k_agg<<<(N + 7) / 8, 256>>>(h1, hn, N);
    k_gemm<<<gemm_grid, 256, smem_gemm>>>(h1, hn, Ws1, Wn1, b1, nullptr, nullptr, out, N, 0);
}

// round 13
// speedup vs baseline: 1.1666x; 1.1666x over previous
#include <cuda_runtime.h>
#include <cuda_bf16.h>
#include <cstdint>

// ---------------- problem constants ----------------
#define NN 100000
#define NE 1600000
#define DD 128

// ---------------- device scratch ----------------
__device__ int   g_deg[NN];
__device__ int   g_incl[NN];
__device__ int   g_rowptr[NN + 1];
__device__ int   g_fill[NN];
__device__ int   g_bsum[128];
__device__ int   g_boff[128];
__device__ int   g_csr[NE];
__device__ float g_invdeg[NN];
// activations as interleaved bf16 (hi,lo) pairs: word = hi | (lo<<16)
__device__ unsigned g_featp[(size_t)NN * DD];
__device__ unsigned g_hnp[(size_t)NN * DD];
__device__ unsigned g_h1p[(size_t)NN * DD];
// weights, transposed (row n, col k), split hi/lo; 4 matrices
__device__ __nv_bfloat16 g_wth[4 * DD * DD];
__device__ __nv_bfloat16 g_wtl[4 * DD * DD];

// ---------------- bf16 pair helpers ----------------
__device__ __forceinline__ unsigned pack_pair(float v) {
    __nv_bfloat16 h = __float2bfloat16(v);
    float r = v - __bfloat162float(h);
    __nv_bfloat16 l = __float2bfloat16(r);
    return (unsigned)__bfloat16_as_ushort(h) | ((unsigned)__bfloat16_as_ushort(l) << 16);
}
__device__ __forceinline__ float unpack_pair(unsigned w) {
    return __bfloat162float(__ushort_as_bfloat16((unsigned short)(w & 0xffffu)))
         + __bfloat162float(__ushort_as_bfloat16((unsigned short)(w >> 16)));
}

__device__ __forceinline__ uint32_t smem_u32(const void* p) {
    uint32_t a;
    asm("{ .reg .u64 t; cvta.to.shared.u64 t, %1; cvt.u32.u64 %0, t; }" : "=r"(a) : "l"(p));
    return a;
}

// ---------------- warp-MMA primitives (base-arch PTX: sm_80+) ----------------
__device__ __forceinline__ void ldsm_x4(uint32_t* r, uint32_t addr) {
    asm volatile("ldmatrix.sync.aligned.m8n8.x4.shared.b16 {%0,%1,%2,%3}, [%4];"
                 : "=r"(r[0]), "=r"(r[1]), "=r"(r[2]), "=r"(r[3]) : "r"(addr));
}
__device__ __forceinline__ void mma16816(float* c, const uint32_t* a,
                                         uint32_t b0, uint32_t b1) {
    asm volatile(
        "mma.sync.aligned.m16n8k16.row.col.f32.bf16.bf16.f32 "
        "{%0,%1,%2,%3}, {%4,%5,%6,%7}, {%8,%9}, {%0,%1,%2,%3};"
        : "+f"(c[0]), "+f"(c[1]), "+f"(c[2]), "+f"(c[3])
        : "r"(a[0]), "r"(a[1]), "r"(a[2]), "r"(a[3]), "r"(b0), "r"(b1));
}

// ---------------- CSR build ----------------
__global__ void k_init(const int* __restrict__ indeg, int N) {
    int i = blockIdx.x * blockDim.x + threadIdx.x;
    if (i < N) {
        g_deg[i] = 0;
        int d = indeg[i];
        if (d < 1) d = 1;
        g_invdeg[i] = 1.0f / (float)d;
    }
}

__global__ void k_count(const int* __restrict__ edst, int E) {
    int e = blockIdx.x * blockDim.x + threadIdx.x;
    if (e < E) atomicAdd(&g_deg[edst[e]], 1);
}

__global__ void k_scan1(int N) {
    __shared__ int s[1024];
    int t = threadIdx.x;
    int i = blockIdx.x * 1024 + t;
    int v = (i < N) ? g_deg[i] : 0;
    s[t] = v;
    __syncthreads();
    #pragma unroll
    for (int off = 1; off < 1024; off <<= 1) {
        int x = (t >= off) ? s[t - off] : 0;
        __syncthreads();
        s[t] += x;
        __syncthreads();
    }
    if (i < N) g_incl[i] = s[t];
    if (t == 1023) g_bsum[blockIdx.x] = s[1023];
}

__global__ void k_scan2(int nb) {
    __shared__ int s[128];
    int t = threadIdx.x;
    int v = (t < nb) ? g_bsum[t] : 0;
    s[t] = v;
    __syncthreads();
    #pragma unroll
    for (int off = 1; off < 128; off <<= 1) {
        int x = (t >= off) ? s[t - off] : 0;
        __syncthreads();
        s[t] += x;
        __syncthreads();
    }
    g_boff[t] = s[t] - v;
}

__global__ void k_scan3(int N) {
    int i = blockIdx.x * blockDim.x + threadIdx.x;
    if (i < N) {
        int b = i >> 10;
        int d = g_deg[i];
        int excl = g_incl[i] - d + g_boff[b];
        g_rowptr[i] = excl;
        g_fill[i]   = excl;
        if (i == N - 1) g_rowptr[N] = excl + d;
    }
}

__global__ void k_fill(const int* __restrict__ esrc, const int* __restrict__ edst, int E) {
    int e = blockIdx.x * blockDim.x + threadIdx.x;
    if (e < E) {
        int d = edst[e];
        int pos = atomicAdd(&g_fill[d], 1);
        g_csr[pos] = esrc[e];
    }
}

// ---------------- feat fp32 -> pair conversion ----------------
__global__ void k_conv(const float* __restrict__ f, unsigned* __restrict__ o, int n4) {
    int i = blockIdx.x * blockDim.x + threadIdx.x;
    if (i < n4) {
        float4 v = __ldg((const float4*)f + i);
        uint4 w;
        w.x = pack_pair(v.x); w.y = pack_pair(v.y);
        w.z = pack_pair(v.z); w.w = pack_pair(v.w);
        ((uint4*)o)[i] = w;
    }
}

// ---------------- weight prep: transpose + hi/lo split ----------------
__global__ void k_wprep(const float* __restrict__ W0, const float* __restrict__ W1,
                        const float* __restrict__ W2, const float* __restrict__ W3) {
    int id = blockIdx.x * blockDim.x + threadIdx.x;  // 0..65535
    int m = id >> 14;
    int r = id & 16383;
    int n = r >> 7, k = r & 127;
    const float* W = (m == 0) ? W0 : (m == 1) ? W1 : (m == 2) ? W2 : W3;
    float v = __ldg(W + k * DD + n);   // transpose: out[n][k] = W[k][n]
    __nv_bfloat16 h = __float2bfloat16(v);
    float rr = v - __bfloat162float(h);
    g_wth[id] = h;
    g_wtl[id] = __float2bfloat16(rr);
}

// ---------------- neighbor mean aggregation (pair in, pair out) ----------------
__global__ void k_agg(const unsigned* __restrict__ hp, unsigned* __restrict__ outp, int N) {
    int w = (blockIdx.x * blockDim.x + threadIdx.x) >> 5;
    int lane = threadIdx.x & 31;
    if (w >= N) return;
    int s0 = g_rowptr[w];
    int s1 = g_rowptr[w + 1];
    float a0 = 0.f, a1 = 0.f, a2 = 0.f, a3 = 0.f;
    for (int base = s0; base < s1; base += 32) {
        int n = s1 - base;
        if (n > 32) n = 32;
        int sid = (base + lane < s1) ? g_csr[base + lane] : 0;
        #pragma unroll 4
        for (int j = 0; j < n; ++j) {
            int s = __shfl_sync(0xffffffffu, sid, j);
            uint4 v = __ldg((const uint4*)(hp + (size_t)s * DD) + lane);
            a0 += unpack_pair(v.x); a1 += unpack_pair(v.y);
            a2 += unpack_pair(v.z); a3 += unpack_pair(v.w);
        }
    }
    float iv = g_invdeg[w];
    uint4 o;
    o.x = pack_pair(a0 * iv); o.y = pack_pair(a1 * iv);
    o.z = pack_pair(a2 * iv); o.w = pack_pair(a3 * iv);
    *((uint4*)(outp + (size_t)w * DD) + lane) = o;
}

// ---------------- warp-MMA dual-GEMM (split bf16) + bias / LN+ReLU ----------------
// D[128x128] = X@Wx + Y@Wy via hi*hi + hi*lo + lo*hi, HMMA m16n8k16.
// 8 warps: wm = wid&3 (32 rows each), wn = wid>>2 (64 cols each).
// SMEM byte offsets:
#define OFF_AH 0
#define OFF_AL 32768
#define OFF_BH 65536
#define OFF_BL 98304
#define OFF_BIAS 131072
#define OFF_G    131584
#define OFF_LB   132096
#define SMEM_MM  132640
// epilogue C reuses [0 .. 128*129*4) with stride 129 floats (conflict-free)

__global__ __launch_bounds__(256, 1)
void k_mm(const unsigned* __restrict__ Xp, const unsigned* __restrict__ Yp,
          const __nv_bfloat16* __restrict__ BxH, const __nv_bfloat16* __restrict__ BxL,
          const __nv_bfloat16* __restrict__ ByH, const __nv_bfloat16* __restrict__ ByL,
          const float* __restrict__ bias, const float* __restrict__ lng,
          const float* __restrict__ lnb,
          float* __restrict__ outf, unsigned* __restrict__ outp, int M, int do_ln) {
    extern __shared__ char smm[];
    uint32_t sb = smem_u32(smm);
    const int t = threadIdx.x;
    const int m0 = blockIdx.x * 128;

    if (t < 128) {
        ((float*)(smm + OFF_BIAS))[t] = __ldg(bias + t);
        if (do_ln) {
            ((float*)(smm + OFF_G))[t]  = __ldg(lng + t);
            ((float*)(smm + OFF_LB))[t] = __ldg(lnb + t);
        }
    }

    const int lane = t & 31, wid = t >> 5;
    const int wm = wid & 3, wn = wid >> 2;
    const int gid = lane >> 2, tig = lane & 3;
    const int sub = lane >> 3, rr = lane & 7;

    float c[2][8][4];
    #pragma unroll
    for (int i = 0; i < 2; ++i)
        #pragma unroll
        for (int j = 0; j < 8; ++j)
            #pragma unroll
            for (int q = 0; q < 4; ++q) c[i][j][q] = 0.f;

    const int r = t >> 1, h = t & 1;   // staging: row 0..127, k-half 0/1
    const int mrow = m0 + r;
    const bool ok = (mrow < M);

    for (int p = 0; p < 2; ++p) {
        const unsigned* Ap = p ? Yp : Xp;
        const __nv_bfloat16* BH = p ? ByH : BxH;
        const __nv_bfloat16* BL = p ? ByL : BxL;
        if (p) __syncthreads();   // prior compute finished reading staging

        // ---- stage A: de-interleave pairs into hi/lo tiles, XOR swizzle ----
        {
            const uint4* asrc = (const uint4*)(Ap + (size_t)mrow * DD + h * 64);
            #pragma unroll
            for (int j = 0; j < 8; ++j) {
                uint4 u0 = ok ? __ldg(asrc + 2 * j)     : make_uint4(0u, 0u, 0u, 0u);
                uint4 u1 = ok ? __ldg(asrc + 2 * j + 1) : make_uint4(0u, 0u, 0u, 0u);
                uint4 hi, lo;
                hi.x = __byte_perm(u0.x, u0.y, 0x5410);
                hi.y = __byte_perm(u0.z, u0.w, 0x5410);
                hi.z = __byte_perm(u1.x, u1.y, 0x5410);
                hi.w = __byte_perm(u1.z, u1.w, 0x5410);
                lo.x = __byte_perm(u0.x, u0.y, 0x7632);
                lo.y = __byte_perm(u0.z, u0.w, 0x7632);
                lo.z = __byte_perm(u1.x, u1.y, 0x7632);
                lo.w = __byte_perm(u1.z, u1.w, 0x7632);
                int chunk = h * 8 + j;
                unsigned off = r * 256 + ((chunk ^ (r & 7)) << 4);
                *(uint4*)(smm + OFF_AH + off) = hi;
                *(uint4*)(smm + OFF_AL + off) = lo;
            }
        }
        // ---- stage B (already [n][k] split in gmem) ----
        {
            const uint4* bh = (const uint4*)(BH + r * DD + h * 64);
            const uint4* bl = (const uint4*)(BL + r * DD + h * 64);
            #pragma unroll
            for (int j = 0; j < 8; ++j) {
                int chunk = h * 8 + j;
                unsigned off = r * 256 + ((chunk ^ (r & 7)) << 4);
                *(uint4*)(smm + OFF_BH + off) = __ldg(bh + j);
                *(uint4*)(smm + OFF_BL + off) = __ldg(bl + j);
            }
        }
        __syncthreads();

        // ---- compute: 3 split products x 8 k-chunks ----
        #pragma unroll
        for (int s = 0; s < 3; ++s) {
            uint32_t sA = sb + ((s == 2) ? OFF_AL : OFF_AH);
            uint32_t sB = sb + ((s == 1) ? OFF_BL : OFF_BH);
            #pragma unroll
            for (int kc = 0; kc < 8; ++kc) {
                uint32_t a[2][4];
                #pragma unroll
                for (int mi = 0; mi < 2; ++mi) {
                    int row = wm * 32 + mi * 16 + (sub & 1) * 8 + rr;
                    int ch  = kc * 2 + (sub >> 1);
                    ldsm_x4(a[mi], sA + row * 256 + ((ch ^ (row & 7)) << 4));
                }
                #pragma unroll
                for (int ni = 0; ni < 4; ++ni) {
                    int row = wn * 64 + ni * 16 + (sub >> 1) * 8 + rr;
                    int ch  = kc * 2 + (sub & 1);
                    uint32_t b[4];
                    ldsm_x4(b, sB + row * 256 + ((ch ^ (row & 7)) << 4));
                    #pragma unroll
                    for (int mi = 0; mi < 2; ++mi) {
                        mma16816(c[mi][2 * ni],     a[mi], b[0], b[1]);
                        mma16816(c[mi][2 * ni + 1], a[mi], b[2], b[3]);
                    }
                }
            }
        }
    }

    // ---- dump C fragments to smem (stride 129 floats) ----
    __syncthreads();
    float* Cs = (float*)smm;
    #pragma unroll
    for (int mi = 0; mi < 2; ++mi) {
        int r0 = wm * 32 + mi * 16 + gid;
        #pragma unroll
        for (int nb = 0; nb < 8; ++nb) {
            int col = wn * 64 + nb * 8 + 2 * tig;
            Cs[r0 * 129 + col]           = c[mi][nb][0];
            Cs[r0 * 129 + col + 1]       = c[mi][nb][1];
            Cs[(r0 + 8) * 129 + col]     = c[mi][nb][2];
            Cs[(r0 + 8) * 129 + col + 1] = c[mi][nb][3];
        }
    }
    __syncthreads();

    // ---- row epilogue: one thread per row ----
    if (t < 128) {
        const float* row = Cs + t * 129;
        const float* smB = (const float*)(smm + OFF_BIAS);
        int m = m0 + t;
        if (do_ln) {
            float s = 0.f, s2 = 0.f;
            #pragma unroll 8
            for (int j = 0; j < 128; ++j) {
                float v = row[j] + smB[j];
                s += v; s2 += v * v;
            }
            float mu  = s * (1.0f / 128.0f);
            float var = s2 * (1.0f / 128.0f) - mu * mu;
            float rs  = rsqrtf(var + 1e-5f);
            if (m < M) {
                const float* gg = (const float*)(smm + OFF_G);
                const float* lb = (const float*)(smm + OFF_LB);
                uint4* dst = (uint4*)(outp + (size_t)m * DD);
                #pragma unroll 4
                for (int j = 0; j < 128; j += 4) {
                    uint4 w;
                    float v0 = fmaxf((row[j]     + smB[j]     - mu) * rs * gg[j]     + lb[j],     0.f);
                    float v1 = fmaxf((row[j + 1] + smB[j + 1] - mu) * rs * gg[j + 1] + lb[j + 1], 0.f);
                    float v2 = fmaxf((row[j + 2] + smB[j + 2] - mu) * rs * gg[j + 2] + lb[j + 2], 0.f);
                    float v3 = fmaxf((row[j + 3] + smB[j + 3] - mu) * rs * gg[j + 3] + lb[j + 3], 0.f);
                    w.x = pack_pair(v0); w.y = pack_pair(v1);
                    w.z = pack_pair(v2); w.w = pack_pair(v3);
                    dst[j >> 2] = w;
                }
            }
        } else if (m < M) {
            float4* dst = (float4*)(outf + (size_t)m * DD);
            #pragma unroll 4
            for (int j = 0; j < 128; j += 4)
                dst[j >> 2] = make_float4(row[j] + smB[j], row[j + 1] + smB[j + 1],
                                          row[j + 2] + smB[j + 2], row[j + 3] + smB[j + 3]);
        }
    }
}

// ---------------- launch ----------------
extern "C" void kernel_launch(void* const* d_in, const int* in_sizes, int n_in,
                              void* d_out, int out_size) {
    const float* feat = (const float*)d_in[0];
    const float* Ws0  = (const float*)d_in[1];
    const float* Wn0  = (const float*)d_in[2];
    const float* b0   = (const float*)d_in[3];
    const float* Ws1  = (const float*)d_in[4];
    const float* Wn1  = (const float*)d_in[5];
    const float* b1   = (const float*)d_in[6];
    const float* lng  = (const float*)d_in[7];
    const float* lnb  = (const float*)d_in[8];
    const int* esrc   = (const int*)d_in[9];
    const int* edst   = (const int*)d_in[10];
    const int* indeg  = (const int*)d_in[11];
    float* out = (float*)d_out;

    const int N = in_sizes[11];
    const int E = in_sizes[9];
    const int NB = (N + 1023) / 1024;

    cudaFuncSetAttribute(k_mm, cudaFuncAttributeMaxDynamicSharedMemorySize, SMEM_MM);

    unsigned *featp = nullptr, *hnp = nullptr, *h1p = nullptr;
    __nv_bfloat16 *wth = nullptr, *wtl = nullptr;
    cudaGetSymbolAddress((void**)&featp, g_featp);
    cudaGetSymbolAddress((void**)&hnp, g_hnp);
    cudaGetSymbolAddress((void**)&h1p, g_h1p);
    cudaGetSymbolAddress((void**)&wth, g_wth);
    cudaGetSymbolAddress((void**)&wtl, g_wtl);

    // CSR build
    k_init <<<(N + 255) / 256, 256>>>(indeg, N);
    k_count<<<(E + 255) / 256, 256>>>(edst, E);
    k_scan1<<<NB, 1024>>>(N);
    k_scan2<<<1, 128>>>(NB);
    k_scan3<<<(N + 255) / 256, 256>>>(N);
    k_fill <<<(E + 255) / 256, 256>>>(esrc, edst, E);

    // conversions
    const int n4 = N * DD / 4;
    k_conv <<<(n4 + 255) / 256, 256>>>(feat, featp, n4);
    k_wprep<<<256, 256>>>(Ws0, Wn0, Ws1, Wn1);

    const int gemm_grid = (N + 127) / 128;

    // layer 0: h1 = relu(LN(feat@Ws0 + agg(feat)@Wn0 + b0)) (pair output)
    k_agg<<<(N + 7) / 8, 256>>>(featp, hnp, N);
    k_mm<<<gemm_grid, 256, SMEM_MM>>>(featp, hnp,
                                      wth + 0 * 16384, wtl + 0 * 16384,
                                      wth + 1 * 16384, wtl + 1 * 16384,
                                      b0, lng, lnb, nullptr, h1p, N, 1);
    // layer 1: out = h1@Ws1 + agg(h1)@Wn1 + b1 (fp32 output)
    k_agg<<<(N + 7) / 8, 256>>>(h1p, hnp, N);
    k_mm<<<gemm_grid, 256, SMEM_MM>>>(h1p, hnp,
                                      wth + 2 * 16384, wtl + 2 * 16384,
                                      wth + 3 * 16384, wtl + 3 * 16384,
                                      b1, nullptr, nullptr, out, nullptr, N, 0);
}